// round 4
// baseline (speedup 1.0000x reference)
#include <cuda_runtime.h>
#include <cuda_bf16.h>
#include <mma.h>

using namespace nvcuda;

// B=4, T=2048, E=1024, H=16, D=64
#define TB 4
#define TT 2048
#define TE 1024
#define TH 16

// ---------------- device scratch ----------------
static __device__ __nv_bfloat16 g_xh[8192 * 1024], g_xl[8192 * 1024];
static __device__ __nv_bfloat16 g_Wah[1024 * 3072], g_Wal[1024 * 3072];
static __device__ __nv_bfloat16 g_Wph[1024 * 1024], g_Wpl[1024 * 1024];
static __device__ __nv_bfloat16 g_qh[8192 * 3072], g_ql[8192 * 3072];
static __device__ __nv_bfloat16 g_yh[8192 * 1024], g_yl[8192 * 1024];

__device__ __forceinline__ void split_bf16(float x, __nv_bfloat16& hi, __nv_bfloat16& lo) {
    hi = __float2bfloat16(x);
    lo = __float2bfloat16(x - __bfloat162float(hi));
}

__device__ __forceinline__ void cp16(void* sptr, const void* gptr) {
    unsigned s = (unsigned)__cvta_generic_to_shared(sptr);
    asm volatile("cp.async.cg.shared.global [%0], [%1], 16;\n" :: "r"(s), "l"(gptr));
}
__device__ __forceinline__ void cp_commit() {
    asm volatile("cp.async.commit_group;\n");
}
__device__ __forceinline__ void cp_wait_all() {
    asm volatile("cp.async.wait_group 0;\n");
}

// ---------------- fp32 -> bf16 hi/lo split (prep) ----------------
__global__ __launch_bounds__(256) void split_kernel(
    const float4* __restrict__ src, __nv_bfloat16* __restrict__ hi,
    __nv_bfloat16* __restrict__ lo, int n4)
{
    int i = blockIdx.x * blockDim.x + threadIdx.x;
    if (i >= n4) return;
    float4 v = src[i];
    float f[4] = {v.x, v.y, v.z, v.w};
    __nv_bfloat16 h[4], l[4];
#pragma unroll
    for (int j = 0; j < 4; j++) split_bf16(f[j], h[j], l[j]);
    *(uint2*)(hi + i * 4) = *(uint2*)h;
    *(uint2*)(lo + i * 4) = *(uint2*)l;
}

// ---------------------------------------------------------------------------
// GEMM: C[M,N] = Ahl[M,K] @ Bhl[K,N] + bias   (3-term bf16, all-bf16 inputs)
// Tile 128x128, BK=32, 256 thr, warp tile 32x64. cp.async double-buffer.
// ---------------------------------------------------------------------------
__global__ __launch_bounds__(256, 2) void gemm_kernel(
    const __nv_bfloat16* __restrict__ Ah_g, const __nv_bfloat16* __restrict__ Al_g,
    const __nv_bfloat16* __restrict__ Bh_g, const __nv_bfloat16* __restrict__ Bl_g,
    const float* __restrict__ bias,
    float* __restrict__ Cf, __nv_bfloat16* __restrict__ Chi, __nv_bfloat16* __restrict__ Clo,
    int M, int N, int K)
{
    extern __shared__ __align__(16) char sm[];
    __nv_bfloat16* Ah = (__nv_bfloat16*)sm;      // [2][128*40]
    __nv_bfloat16* Al = Ah + 2 * 5120;
    __nv_bfloat16* Bh = Al + 2 * 5120;           // [2][32*136]
    __nv_bfloat16* Bl = Bh + 2 * 4352;

    const int tid = threadIdx.x;
    const int wid = tid >> 5;
    const int lane = tid & 31;
    const int warp_row = wid >> 1;   // 0..3 (32 rows)
    const int warp_col = wid & 1;    // 0..1 (64 cols)
    const int bm = blockIdx.y * 128;
    const int bn = blockIdx.x * 128;

    wmma::fragment<wmma::accumulator, 16, 16, 16, float> acc[2][4];
#pragma unroll
    for (int mm = 0; mm < 2; mm++)
#pragma unroll
        for (int nn = 0; nn < 4; nn++) wmma::fill_fragment(acc[mm][nn], 0.0f);

    // prefetch helper (inlined twice)
#define GEMM_PREFETCH(KT, ST)                                                        \
    {                                                                                \
        int k0 = (KT) * 32;                                                          \
        _Pragma("unroll")                                                            \
        for (int jj = 0; jj < 2; jj++) {                                             \
            int idx = tid * 2 + jj;                                                  \
            int row = idx >> 2, ch = idx & 3;                                        \
            size_t g = (size_t)(bm + row) * K + k0 + ch * 8;                         \
            cp16(&Ah[(ST) * 5120 + row * 40 + ch * 8], Ah_g + g);                    \
            cp16(&Al[(ST) * 5120 + row * 40 + ch * 8], Al_g + g);                    \
        }                                                                            \
        _Pragma("unroll")                                                            \
        for (int jj = 0; jj < 2; jj++) {                                             \
            int idx = tid * 2 + jj;                                                  \
            int row = idx >> 4, ch = idx & 15;                                       \
            size_t g = (size_t)(k0 + row) * N + bn + ch * 8;                         \
            cp16(&Bh[(ST) * 4352 + row * 136 + ch * 8], Bh_g + g);                   \
            cp16(&Bl[(ST) * 4352 + row * 136 + ch * 8], Bl_g + g);                   \
        }                                                                            \
        cp_commit();                                                                 \
    }

    GEMM_PREFETCH(0, 0);

    const int NK = K >> 5;
    for (int kt = 0; kt < NK; kt++) {
        cp_wait_all();
        __syncthreads();
        if (kt + 1 < NK) { GEMM_PREFETCH(kt + 1, (kt + 1) & 1); }

        const int st = kt & 1;
        const __nv_bfloat16* Ahc = Ah + st * 5120;
        const __nv_bfloat16* Alc = Al + st * 5120;
        const __nv_bfloat16* Bhc = Bh + st * 4352;
        const __nv_bfloat16* Blc = Bl + st * 4352;

#pragma unroll
        for (int ks = 0; ks < 2; ks++) {
            const int kk = ks * 16;
            wmma::fragment<wmma::matrix_a, 16, 16, 16, __nv_bfloat16, wmma::row_major> ah[2], al[2];
#pragma unroll
            for (int mm = 0; mm < 2; mm++) {
                wmma::load_matrix_sync(ah[mm], Ahc + (warp_row * 32 + mm * 16) * 40 + kk, 40);
                wmma::load_matrix_sync(al[mm], Alc + (warp_row * 32 + mm * 16) * 40 + kk, 40);
            }
#pragma unroll
            for (int nn = 0; nn < 4; nn++) {
                wmma::fragment<wmma::matrix_b, 16, 16, 16, __nv_bfloat16, wmma::row_major> bh, bl;
                wmma::load_matrix_sync(bh, Bhc + kk * 136 + warp_col * 64 + nn * 16, 136);
                wmma::load_matrix_sync(bl, Blc + kk * 136 + warp_col * 64 + nn * 16, 136);
#pragma unroll
                for (int mm = 0; mm < 2; mm++) {
                    wmma::mma_sync(acc[mm][nn], ah[mm], bh, acc[mm][nn]);
                    wmma::mma_sync(acc[mm][nn], ah[mm], bl, acc[mm][nn]);
                    wmma::mma_sync(acc[mm][nn], al[mm], bh, acc[mm][nn]);
                }
            }
        }
        __syncthreads();
    }

    // Epilogue: per-warp 32x36 fp32 patch in smem
    float* patch = (float*)sm + wid * 1152;
    const int crow = bm + warp_row * 32;
#pragma unroll
    for (int hh = 0; hh < 2; hh++) {
        wmma::store_matrix_sync(patch, acc[0][2 * hh], 36, wmma::mem_row_major);
        wmma::store_matrix_sync(patch + 16, acc[0][2 * hh + 1], 36, wmma::mem_row_major);
        wmma::store_matrix_sync(patch + 16 * 36, acc[1][2 * hh], 36, wmma::mem_row_major);
        wmma::store_matrix_sync(patch + 16 * 36 + 16, acc[1][2 * hh + 1], 36, wmma::mem_row_major);
        __syncwarp();
        const int ccol = bn + warp_col * 64 + hh * 32;
        for (int i = lane; i < 1024; i += 32) {
            int r = i >> 5, c = i & 31;
            float val = patch[r * 36 + c] + bias[ccol + c];
            size_t idx = (size_t)(crow + r) * N + ccol + c;
            if (Chi) {
                __nv_bfloat16 hi, lo;
                split_bf16(val, hi, lo);
                Chi[idx] = hi;
                Clo[idx] = lo;
            } else {
                Cf[idx] = val;
            }
        }
        __syncwarp();
    }
}

// ---------------------------------------------------------------------------
// Flash attention (causal). Block = 128 query rows x one (b,h).
// 8 warps; warp owns 16 query rows end-to-end -> 1 __syncthreads per KV iter.
// KV tiles of 64, cp.async double-buffered. 3-term bf16 MMAs.
// ---------------------------------------------------------------------------
__global__ __launch_bounds__(256, 1) void attn_kernel()
{
    extern __shared__ __align__(16) char sm[];
    __nv_bfloat16* Qh = (__nv_bfloat16*)sm;        // [128][72]
    __nv_bfloat16* Ql = Qh + 9216;
    __nv_bfloat16* Kh = Ql + 9216;                 // [2][64][72]
    __nv_bfloat16* Kl = Kh + 2 * 4608;
    __nv_bfloat16* Vh = Kl + 2 * 4608;
    __nv_bfloat16* Vl = Vh + 2 * 4608;
    __nv_bfloat16* Ph = Vl + 2 * 4608;             // [128][72]
    __nv_bfloat16* Pl = Ph + 9216;
    float* Ss = (float*)(Pl + 9216);               // [128][68]
    float* Os = Ss + 128 * 68;                     // [128][68]
    float* row_m = Os + 128 * 68;                  // [128]
    float* row_l = row_m + 128;

    const int tid = threadIdx.x;
    const int wid = tid >> 5;
    const int lane = tid & 31;
    const int qt = (gridDim.x - 1) - blockIdx.x;   // heavy tiles first
    const int qs = qt * 128;
    const int bh = blockIdx.y;
    const int b = bh >> 4, h = bh & 15;

#define ATTN_LOADKV(J, ST)                                                           \
    {                                                                                \
        size_t base = (size_t)(b * TT + (J) * 64) * 3072 + h * 64;                   \
        _Pragma("unroll")                                                            \
        for (int jj = 0; jj < 2; jj++) {                                             \
            int idx = tid * 2 + jj;                                                  \
            int row = idx >> 3, ch = idx & 7;                                        \
            size_t g = base + (size_t)row * 3072 + ch * 8;                           \
            cp16(&Kh[(ST) * 4608 + row * 72 + ch * 8], g_qh + 1024 + g);             \
            cp16(&Kl[(ST) * 4608 + row * 72 + ch * 8], g_ql + 1024 + g);             \
            cp16(&Vh[(ST) * 4608 + row * 72 + ch * 8], g_qh + 2048 + g);             \
            cp16(&Vl[(ST) * 4608 + row * 72 + ch * 8], g_ql + 2048 + g);             \
        }                                                                            \
        cp_commit();                                                                 \
    }

    // Q tile + first KV tile
#pragma unroll
    for (int jj = 0; jj < 4; jj++) {
        int idx = tid * 4 + jj;
        int row = idx >> 3, ch = idx & 7;
        size_t g = (size_t)(b * TT + qs + row) * 3072 + h * 64 + ch * 8;
        cp16(&Qh[row * 72 + ch * 8], g_qh + g);
        cp16(&Ql[row * 72 + ch * 8], g_ql + g);
    }
    ATTN_LOADKV(0, 0);

    for (int i = tid; i < 128 * 68; i += 256) Os[i] = 0.0f;
    if (tid < 128) { row_m[tid] = -1e30f; row_l[tid] = 0.0f; }

    const int jmax = 2 * qt + 1;
    for (int j = 0; j <= jmax; j++) {
        cp_wait_all();
        __syncthreads();
        if (j < jmax) { ATTN_LOADKV(j + 1, (j + 1) & 1); }

        const int st = j & 1;
        const __nv_bfloat16* Khc = Kh + st * 4608;
        const __nv_bfloat16* Klc = Kl + st * 4608;
        const __nv_bfloat16* Vhc = Vh + st * 4608;
        const __nv_bfloat16* Vlc = Vl + st * 4608;

        // ---- S = Q @ K^T (warp rows wid*16..+15, 64 cols) ----
        {
            wmma::fragment<wmma::accumulator, 16, 16, 16, float> sa[4];
#pragma unroll
            for (int nn = 0; nn < 4; nn++) wmma::fill_fragment(sa[nn], 0.0f);
#pragma unroll
            for (int kk = 0; kk < 64; kk += 16) {
                wmma::fragment<wmma::matrix_a, 16, 16, 16, __nv_bfloat16, wmma::row_major> ah, al;
                wmma::load_matrix_sync(ah, Qh + (wid * 16) * 72 + kk, 72);
                wmma::load_matrix_sync(al, Ql + (wid * 16) * 72 + kk, 72);
#pragma unroll
                for (int nn = 0; nn < 4; nn++) {
                    wmma::fragment<wmma::matrix_b, 16, 16, 16, __nv_bfloat16, wmma::col_major> bh2, bl2;
                    wmma::load_matrix_sync(bh2, Khc + (nn * 16) * 72 + kk, 72);
                    wmma::load_matrix_sync(bl2, Klc + (nn * 16) * 72 + kk, 72);
                    wmma::mma_sync(sa[nn], ah, bh2, sa[nn]);
                    wmma::mma_sync(sa[nn], ah, bl2, sa[nn]);
                    wmma::mma_sync(sa[nn], al, bh2, sa[nn]);
                }
            }
#pragma unroll
            for (int nn = 0; nn < 4; nn++)
                wmma::store_matrix_sync(Ss + (wid * 16) * 68 + nn * 16, sa[nn], 68,
                                        wmma::mem_row_major);
        }
        __syncwarp();

        // ---- softmax on own 16 rows (warp-private) ----
#pragma unroll
        for (int rr = 0; rr < 16; rr++) {
            int row = wid * 16 + rr;
            int row_g = qs + row;
            float s0 = Ss[row * 68 + lane] * 0.125f;
            float s1 = Ss[row * 68 + 32 + lane] * 0.125f;
            if (j * 64 + 63 > row_g) {
                if (j * 64 + lane > row_g) s0 = -1e30f;
                if (j * 64 + 32 + lane > row_g) s1 = -1e30f;
            }
            float mt = fmaxf(s0, s1);
#pragma unroll
            for (int off = 16; off; off >>= 1)
                mt = fmaxf(mt, __shfl_xor_sync(0xFFFFFFFFu, mt, off));
            float mo = row_m[row];
            float mn = fmaxf(mo, mt);
            float alpha = __expf(mo - mn);
            float p0 = __expf(s0 - mn);
            float p1 = __expf(s1 - mn);
            __nv_bfloat16 hi, lo;
            split_bf16(p0, hi, lo);
            Ph[row * 72 + lane] = hi; Pl[row * 72 + lane] = lo;
            split_bf16(p1, hi, lo);
            Ph[row * 72 + 32 + lane] = hi; Pl[row * 72 + 32 + lane] = lo;
            float psum = p0 + p1;
#pragma unroll
            for (int off = 16; off; off >>= 1)
                psum += __shfl_xor_sync(0xFFFFFFFFu, psum, off);
            if (lane == 0) {
                row_m[row] = mn;
                row_l[row] = alpha * row_l[row] + psum;
            }
            Os[row * 68 + lane] *= alpha;
            Os[row * 68 + 32 + lane] *= alpha;
        }
        __syncwarp();

        // ---- O += P @ V (warp-private rows) ----
        {
            wmma::fragment<wmma::accumulator, 16, 16, 16, float> oa[4];
#pragma unroll
            for (int nn = 0; nn < 4; nn++)
                wmma::load_matrix_sync(oa[nn], Os + (wid * 16) * 68 + nn * 16, 68,
                                       wmma::mem_row_major);
#pragma unroll
            for (int kk = 0; kk < 64; kk += 16) {
                wmma::fragment<wmma::matrix_a, 16, 16, 16, __nv_bfloat16, wmma::row_major> ph, pl;
                wmma::load_matrix_sync(ph, Ph + (wid * 16) * 72 + kk, 72);
                wmma::load_matrix_sync(pl, Pl + (wid * 16) * 72 + kk, 72);
#pragma unroll
                for (int nn = 0; nn < 4; nn++) {
                    wmma::fragment<wmma::matrix_b, 16, 16, 16, __nv_bfloat16, wmma::row_major> vh, vl;
                    wmma::load_matrix_sync(vh, Vhc + kk * 72 + nn * 16, 72);
                    wmma::load_matrix_sync(vl, Vlc + kk * 72 + nn * 16, 72);
                    wmma::mma_sync(oa[nn], ph, vh, oa[nn]);
                    wmma::mma_sync(oa[nn], ph, vl, oa[nn]);
                    wmma::mma_sync(oa[nn], pl, vh, oa[nn]);
                }
            }
#pragma unroll
            for (int nn = 0; nn < 4; nn++)
                wmma::store_matrix_sync(Os + (wid * 16) * 68 + nn * 16, oa[nn], 68,
                                        wmma::mem_row_major);
        }
        __syncwarp();
    }

    // ---- normalize + write y as bf16 hi/lo (2 cols per lane, 4B stores) ----
#pragma unroll
    for (int rr = 0; rr < 16; rr++) {
        int row = wid * 16 + rr;
        float inv = 1.0f / row_l[row];
        size_t base = (size_t)(b * TT + qs + row) * 1024 + h * 64;
        float v0 = Os[row * 68 + 2 * lane] * inv;
        float v1 = Os[row * 68 + 2 * lane + 1] * inv;
        __nv_bfloat16 h0, l0, h1, l1;
        split_bf16(v0, h0, l0);
        split_bf16(v1, h1, l1);
        __nv_bfloat162 ph2; ph2.x = h0; ph2.y = h1;
        __nv_bfloat162 pl2; pl2.x = l0; pl2.y = l1;
        *(__nv_bfloat162*)(g_yh + base + 2 * lane) = ph2;
        *(__nv_bfloat162*)(g_yl + base + 2 * lane) = pl2;
    }
}

// ---------------------------------------------------------------------------
// kernel_launch
// Inputs: 0=x, 1=mask (causal known), 2=W_attn, 3=b_attn, 4=W_proj, 5=b_proj.
// ---------------------------------------------------------------------------
extern "C" void kernel_launch(void* const* d_in, const int* in_sizes, int n_in,
                              void* d_out, int out_size)
{
    const float* x  = (const float*)d_in[0];
    const float* Wa = (const float*)d_in[2];
    const float* ba = (const float*)d_in[3];
    const float* Wp = (const float*)d_in[4];
    const float* bp = (const float*)d_in[5];
    float* out = (float*)d_out;

    void *xh, *xl, *Wah, *Wal, *Wph, *Wpl, *qh, *ql, *yh, *yl;
    cudaGetSymbolAddress(&xh, g_xh);   cudaGetSymbolAddress(&xl, g_xl);
    cudaGetSymbolAddress(&Wah, g_Wah); cudaGetSymbolAddress(&Wal, g_Wal);
    cudaGetSymbolAddress(&Wph, g_Wph); cudaGetSymbolAddress(&Wpl, g_Wpl);
    cudaGetSymbolAddress(&qh, g_qh);   cudaGetSymbolAddress(&ql, g_ql);
    cudaGetSymbolAddress(&yh, g_yh);   cudaGetSymbolAddress(&yl, g_yl);

    static int attr_set = 0;
    cudaFuncSetAttribute((const void*)gemm_kernel,
                         cudaFuncAttributeMaxDynamicSharedMemorySize, 75776);
    cudaFuncSetAttribute((const void*)attn_kernel,
                         cudaFuncAttributeMaxDynamicSharedMemorySize, 218112);
    (void)attr_set;

    // prep: fp32 -> bf16 hi/lo
    split_kernel<<<8192, 256>>>((const float4*)x,  (__nv_bfloat16*)xh,  (__nv_bfloat16*)xl,  8192 * 1024 / 4);
    split_kernel<<<3072, 256>>>((const float4*)Wa, (__nv_bfloat16*)Wah, (__nv_bfloat16*)Wal, 1024 * 3072 / 4);
    split_kernel<<<1024, 256>>>((const float4*)Wp, (__nv_bfloat16*)Wph, (__nv_bfloat16*)Wpl, 1024 * 1024 / 4);

    // qkv = x @ W_attn + b_attn  -> bf16 hi/lo
    gemm_kernel<<<dim3(3072 / 128, 8192 / 128), 256, 75776>>>(
        (const __nv_bfloat16*)xh, (const __nv_bfloat16*)xl,
        (const __nv_bfloat16*)Wah, (const __nv_bfloat16*)Wal,
        ba, nullptr, (__nv_bfloat16*)qh, (__nv_bfloat16*)ql,
        8192, 3072, 1024);

    // y = causal MHA(qkv) -> bf16 hi/lo
    attn_kernel<<<dim3(TT / 128, TB * TH), 256, 218112>>>();

    // out = y @ W_proj + b_proj -> fp32
    gemm_kernel<<<dim3(1024 / 128, 8192 / 128), 256, 75776>>>(
        (const __nv_bfloat16*)yh, (const __nv_bfloat16*)yl,
        (const __nv_bfloat16*)Wph, (const __nv_bfloat16*)Wpl,
        bp, out, nullptr, nullptr,
        8192, 1024, 1024);
}

// round 6
// speedup vs baseline: 1.4182x; 1.4182x over previous
#include <cstdint>
#include <cuda_runtime.h>
#include <cuda_bf16.h>
#include <mma.h>

using namespace nvcuda;

// B=4, T=2048, E=1024, H=16, D=64
#define TB 4
#define TT 2048
#define TE 1024
#define TH 16

// ---------------- device scratch ----------------
static __device__ __nv_bfloat16 g_xh[8192 * 1024], g_xl[8192 * 1024];
static __device__ __nv_bfloat16 g_Wah[1024 * 3072], g_Wal[1024 * 3072];
static __device__ __nv_bfloat16 g_Wph[1024 * 1024], g_Wpl[1024 * 1024];
static __device__ __nv_bfloat16 g_qh[8192 * 3072], g_ql[8192 * 3072];
static __device__ __nv_bfloat16 g_yh[8192 * 1024], g_yl[8192 * 1024];

__device__ __forceinline__ void split_bf16(float x, __nv_bfloat16& hi, __nv_bfloat16& lo) {
    hi = __float2bfloat16(x);
    lo = __float2bfloat16(x - __bfloat162float(hi));
}

__device__ __forceinline__ void cp16(void* sptr, const void* gptr) {
    unsigned s = (unsigned)__cvta_generic_to_shared(sptr);
    asm volatile("cp.async.cg.shared.global [%0], [%1], 16;\n" :: "r"(s), "l"(gptr));
}
__device__ __forceinline__ void cp_commit() {
    asm volatile("cp.async.commit_group;\n");
}
__device__ __forceinline__ void cp_wait_all() {
    asm volatile("cp.async.wait_group 0;\n");
}

// mma.sync m16n8k16 row.col bf16 -> f32, D += A*B
#define MMA_BF16(d, a, b0_, b1_)                                                  \
    asm volatile(                                                                 \
        "mma.sync.aligned.m16n8k16.row.col.f32.bf16.bf16.f32 "                    \
        "{%0,%1,%2,%3}, {%4,%5,%6,%7}, {%8,%9}, {%0,%1,%2,%3};\n"                 \
        : "+f"((d)[0]), "+f"((d)[1]), "+f"((d)[2]), "+f"((d)[3])                  \
        : "r"((a)[0]), "r"((a)[1]), "r"((a)[2]), "r"((a)[3]), "r"(b0_), "r"(b1_))

__device__ __forceinline__ unsigned pack_bf16x2(float e0, float e1) {
    __nv_bfloat162 t = __floats2bfloat162_rn(e0, e1);  // .x=e0 (low), .y=e1
    unsigned r;
    *(__nv_bfloat162*)&r = t;
    return r;
}

// ---------------- fp32 -> bf16 hi/lo split (prep) ----------------
__global__ __launch_bounds__(256) void split_kernel(
    const float4* __restrict__ src, __nv_bfloat16* __restrict__ hi,
    __nv_bfloat16* __restrict__ lo, int n4)
{
    int i = blockIdx.x * blockDim.x + threadIdx.x;
    if (i >= n4) return;
    float4 v = src[i];
    float f[4] = {v.x, v.y, v.z, v.w};
    __nv_bfloat16 h[4], l[4];
#pragma unroll
    for (int j = 0; j < 4; j++) split_bf16(f[j], h[j], l[j]);
    *(uint2*)(hi + i * 4) = *(uint2*)h;
    *(uint2*)(lo + i * 4) = *(uint2*)l;
}

// ---------------------------------------------------------------------------
// GEMM: C[M,N] = Ahl[M,K] @ Bhl[K,N] + bias   (3-term bf16)
// Tile 128x128, BK=32, 256 thr, warp tile 32x64. cp.async double-buffer.
// ---------------------------------------------------------------------------
__global__ __launch_bounds__(256, 2) void gemm_kernel(
    const __nv_bfloat16* __restrict__ Ah_g, const __nv_bfloat16* __restrict__ Al_g,
    const __nv_bfloat16* __restrict__ Bh_g, const __nv_bfloat16* __restrict__ Bl_g,
    const float* __restrict__ bias,
    float* __restrict__ Cf, __nv_bfloat16* __restrict__ Chi, __nv_bfloat16* __restrict__ Clo,
    int M, int N, int K)
{
    extern __shared__ __align__(16) char sm[];
    __nv_bfloat16* Ah = (__nv_bfloat16*)sm;      // [2][128*40]
    __nv_bfloat16* Al = Ah + 2 * 5120;
    __nv_bfloat16* Bh = Al + 2 * 5120;           // [2][32*136]
    __nv_bfloat16* Bl = Bh + 2 * 4352;

    const int tid = threadIdx.x;
    const int wid = tid >> 5;
    const int lane = tid & 31;
    const int warp_row = wid >> 1;
    const int warp_col = wid & 1;
    const int bm = blockIdx.y * 128;
    const int bn = blockIdx.x * 128;

    wmma::fragment<wmma::accumulator, 16, 16, 16, float> acc[2][4];
#pragma unroll
    for (int mm = 0; mm < 2; mm++)
#pragma unroll
        for (int nn = 0; nn < 4; nn++) wmma::fill_fragment(acc[mm][nn], 0.0f);

#define GEMM_PREFETCH(KT, ST)                                                        \
    {                                                                                \
        int k0 = (KT) * 32;                                                          \
        _Pragma("unroll")                                                            \
        for (int jj = 0; jj < 2; jj++) {                                             \
            int idx = tid * 2 + jj;                                                  \
            int row = idx >> 2, ch = idx & 3;                                        \
            size_t g = (size_t)(bm + row) * K + k0 + ch * 8;                         \
            cp16(&Ah[(ST) * 5120 + row * 40 + ch * 8], Ah_g + g);                    \
            cp16(&Al[(ST) * 5120 + row * 40 + ch * 8], Al_g + g);                    \
        }                                                                            \
        _Pragma("unroll")                                                            \
        for (int jj = 0; jj < 2; jj++) {                                             \
            int idx = tid * 2 + jj;                                                  \
            int row = idx >> 4, ch = idx & 15;                                       \
            size_t g = (size_t)(k0 + row) * N + bn + ch * 8;                         \
            cp16(&Bh[(ST) * 4352 + row * 136 + ch * 8], Bh_g + g);                   \
            cp16(&Bl[(ST) * 4352 + row * 136 + ch * 8], Bl_g + g);                   \
        }                                                                            \
        cp_commit();                                                                 \
    }

    GEMM_PREFETCH(0, 0);

    const int NK = K >> 5;
    for (int kt = 0; kt < NK; kt++) {
        cp_wait_all();
        __syncthreads();
        if (kt + 1 < NK) { GEMM_PREFETCH(kt + 1, (kt + 1) & 1); }

        const int st = kt & 1;
        const __nv_bfloat16* Ahc = Ah + st * 5120;
        const __nv_bfloat16* Alc = Al + st * 5120;
        const __nv_bfloat16* Bhc = Bh + st * 4352;
        const __nv_bfloat16* Blc = Bl + st * 4352;

#pragma unroll
        for (int ks = 0; ks < 2; ks++) {
            const int kk = ks * 16;
            wmma::fragment<wmma::matrix_a, 16, 16, 16, __nv_bfloat16, wmma::row_major> ah[2], al[2];
#pragma unroll
            for (int mm = 0; mm < 2; mm++) {
                wmma::load_matrix_sync(ah[mm], Ahc + (warp_row * 32 + mm * 16) * 40 + kk, 40);
                wmma::load_matrix_sync(al[mm], Alc + (warp_row * 32 + mm * 16) * 40 + kk, 40);
            }
#pragma unroll
            for (int nn = 0; nn < 4; nn++) {
                wmma::fragment<wmma::matrix_b, 16, 16, 16, __nv_bfloat16, wmma::row_major> bh, bl;
                wmma::load_matrix_sync(bh, Bhc + kk * 136 + warp_col * 64 + nn * 16, 136);
                wmma::load_matrix_sync(bl, Blc + kk * 136 + warp_col * 64 + nn * 16, 136);
#pragma unroll
                for (int mm = 0; mm < 2; mm++) {
                    wmma::mma_sync(acc[mm][nn], ah[mm], bh, acc[mm][nn]);
                    wmma::mma_sync(acc[mm][nn], ah[mm], bl, acc[mm][nn]);
                    wmma::mma_sync(acc[mm][nn], al[mm], bh, acc[mm][nn]);
                }
            }
        }
        __syncthreads();
    }

    // Epilogue
    float* patch = (float*)sm + wid * 1152;
    const int crow = bm + warp_row * 32;
#pragma unroll
    for (int hh = 0; hh < 2; hh++) {
        wmma::store_matrix_sync(patch, acc[0][2 * hh], 36, wmma::mem_row_major);
        wmma::store_matrix_sync(patch + 16, acc[0][2 * hh + 1], 36, wmma::mem_row_major);
        wmma::store_matrix_sync(patch + 16 * 36, acc[1][2 * hh], 36, wmma::mem_row_major);
        wmma::store_matrix_sync(patch + 16 * 36 + 16, acc[1][2 * hh + 1], 36, wmma::mem_row_major);
        __syncwarp();
        const int ccol = bn + warp_col * 64 + hh * 32;
        for (int i = lane; i < 1024; i += 32) {
            int r = i >> 5, c = i & 31;
            float val = patch[r * 36 + c] + bias[ccol + c];
            size_t idx = (size_t)(crow + r) * N + ccol + c;
            if (Chi) {
                __nv_bfloat16 hi, lo;
                split_bf16(val, hi, lo);
                Chi[idx] = hi;
                Clo[idx] = lo;
            } else {
                Cf[idx] = val;
            }
        }
        __syncwarp();
    }
}

// ---------------------------------------------------------------------------
// Flash attention (causal), register-resident FA2 style with raw mma.sync.
// Block = 128 query rows x one (b,h); 8 warps x 16 rows; KV tiles of 64.
// O accum, softmax stats, P fragments all in registers. smem: K/V only.
// ---------------------------------------------------------------------------
__global__ __launch_bounds__(256, 1) void attn_kernel()
{
    extern __shared__ __align__(16) char sm[];
    __nv_bfloat16* Kh  = (__nv_bfloat16*)sm;       // [2][64*72]
    __nv_bfloat16* Kl  = Kh + 2 * 4608;
    __nv_bfloat16* Vrh = Kl + 2 * 4608;            // raw V [2][64*72]
    __nv_bfloat16* Vrl = Vrh + 2 * 4608;
    __nv_bfloat16* Vth = Vrl + 2 * 4608;           // V^T [64d][72kv]
    __nv_bfloat16* Vtl = Vth + 4608;

    const int tid = threadIdx.x;
    const int wid = tid >> 5;
    const int lane = tid & 31;
    const int qt = (gridDim.x - 1) - blockIdx.x;   // heavy tiles first
    const int qs = qt * 128;
    const int bh = blockIdx.y;
    const int b = bh >> 4, h = bh & 15;
    const int wrow = wid * 16;

    const int lrow = lane >> 2;          // 0..7
    const int lk   = (lane & 3) * 2;     // 0,2,4,6

#define ATTN_LOADKV(J, ST)                                                           \
    {                                                                                \
        size_t base = (size_t)(b * TT + (J) * 64) * 3072 + h * 64;                   \
        _Pragma("unroll")                                                            \
        for (int jj = 0; jj < 2; jj++) {                                             \
            int idx = tid * 2 + jj;                                                  \
            int row = idx >> 3, ch = idx & 7;                                        \
            size_t g = base + (size_t)row * 3072 + ch * 8;                           \
            cp16(&Kh[(ST) * 4608 + row * 72 + ch * 8], g_qh + 1024 + g);             \
            cp16(&Kl[(ST) * 4608 + row * 72 + ch * 8], g_ql + 1024 + g);             \
            cp16(&Vrh[(ST) * 4608 + row * 72 + ch * 8], g_qh + 2048 + g);            \
            cp16(&Vrl[(ST) * 4608 + row * 72 + ch * 8], g_ql + 2048 + g);            \
        }                                                                            \
        cp_commit();                                                                 \
    }

    ATTN_LOADKV(0, 0);

    // ---- Q fragments from gmem (one-time) ----
    // A-frag m16n8k16: a0=(r,k), a1=(r+8,k), a2=(r,k+8), a3=(r+8,k+8)
    unsigned qhf[4][4], qlf[4][4];
    {
        const int r0 = qs + wrow + lrow;
        size_t base0 = (size_t)(b * TT + r0) * 3072 + h * 64;
        size_t base1 = base0 + (size_t)8 * 3072;
#pragma unroll
        for (int kc = 0; kc < 4; kc++) {
            int k0 = kc * 16 + lk;
            qhf[kc][0] = *(const unsigned*)(g_qh + base0 + k0);
            qhf[kc][1] = *(const unsigned*)(g_qh + base1 + k0);
            qhf[kc][2] = *(const unsigned*)(g_qh + base0 + k0 + 8);
            qhf[kc][3] = *(const unsigned*)(g_qh + base1 + k0 + 8);
            qlf[kc][0] = *(const unsigned*)(g_ql + base0 + k0);
            qlf[kc][1] = *(const unsigned*)(g_ql + base1 + k0);
            qlf[kc][2] = *(const unsigned*)(g_ql + base0 + k0 + 8);
            qlf[kc][3] = *(const unsigned*)(g_ql + base1 + k0 + 8);
        }
    }

    float oacc[8][4];
#pragma unroll
    for (int nt = 0; nt < 8; nt++)
#pragma unroll
        for (int e = 0; e < 4; e++) oacc[nt][e] = 0.0f;
    float m0 = -1e30f, m1 = -1e30f, l0 = 0.0f, l1 = 0.0f;

    const int r0g = qs + wrow + lrow;
    const int r1g = r0g + 8;
    const int jmax = 2 * qt + 1;

    for (int j = 0; j <= jmax; j++) {
        cp_wait_all();
        __syncthreads();
        const int st = j & 1;
        if (j < jmax) { ATTN_LOADKV(j + 1, st ^ 1); }

        // ---- transpose V(st) -> Vt (all warps) ----
        {
            const __nv_bfloat16* vh = Vrh + st * 4608;
            const __nv_bfloat16* vl = Vrl + st * 4608;
            for (int i = tid; i < 4096; i += 256) {
                int r = i >> 6, c = i & 63;
                Vth[c * 72 + r] = vh[r * 72 + c];
                Vtl[c * 72 + r] = vl[r * 72 + c];
            }
        }
        __syncthreads();

        if (j * 64 > qs + wrow + 15) continue;  // whole warp masked

        const __nv_bfloat16* Khs = Kh + st * 4608;
        const __nv_bfloat16* Kls = Kl + st * 4608;

        // ---- S = Q @ K^T (registers) ----
        float sacc[8][4];
#pragma unroll
        for (int nt = 0; nt < 8; nt++) {
            sacc[nt][0] = sacc[nt][1] = sacc[nt][2] = sacc[nt][3] = 0.0f;
            const __nv_bfloat16* kbh = Khs + (nt * 8 + lrow) * 72 + lk;
            const __nv_bfloat16* kbl = Kls + (nt * 8 + lrow) * 72 + lk;
#pragma unroll
            for (int kc = 0; kc < 4; kc++) {
                unsigned bh0 = *(const unsigned*)(kbh + kc * 16);
                unsigned bh1 = *(const unsigned*)(kbh + kc * 16 + 8);
                unsigned bl0 = *(const unsigned*)(kbl + kc * 16);
                unsigned bl1 = *(const unsigned*)(kbl + kc * 16 + 8);
                MMA_BF16(sacc[nt], qhf[kc], bh0, bh1);
                MMA_BF16(sacc[nt], qhf[kc], bl0, bl1);
                MMA_BF16(sacc[nt], qlf[kc], bh0, bh1);
            }
        }

        // ---- softmax (registers; rows r0g, r1g per lane) ----
        const bool needmask = (j * 64 + 63 > qs + wrow);
        float mt0 = -1e30f, mt1 = -1e30f;
#pragma unroll
        for (int nt = 0; nt < 8; nt++) {
            float* s = sacc[nt];
            s[0] *= 0.125f; s[1] *= 0.125f; s[2] *= 0.125f; s[3] *= 0.125f;
            if (needmask) {
                int c0 = j * 64 + nt * 8 + lk;
                if (c0     > r0g) s[0] = -1e30f;
                if (c0 + 1 > r0g) s[1] = -1e30f;
                if (c0     > r1g) s[2] = -1e30f;
                if (c0 + 1 > r1g) s[3] = -1e30f;
            }
            mt0 = fmaxf(mt0, fmaxf(s[0], s[1]));
            mt1 = fmaxf(mt1, fmaxf(s[2], s[3]));
        }
        mt0 = fmaxf(mt0, __shfl_xor_sync(0xFFFFFFFFu, mt0, 1));
        mt0 = fmaxf(mt0, __shfl_xor_sync(0xFFFFFFFFu, mt0, 2));
        mt1 = fmaxf(mt1, __shfl_xor_sync(0xFFFFFFFFu, mt1, 1));
        mt1 = fmaxf(mt1, __shfl_xor_sync(0xFFFFFFFFu, mt1, 2));
        float mn0 = fmaxf(m0, mt0), mn1 = fmaxf(m1, mt1);
        float a0 = __expf(m0 - mn0), a1 = __expf(m1 - mn1);
        m0 = mn0; m1 = mn1;

        float ps0 = 0.0f, ps1 = 0.0f;
        unsigned pah[4][4], pal[4][4];
#pragma unroll
        for (int nt = 0; nt < 8; nt++) {
            float* s = sacc[nt];
            float p0 = __expf(s[0] - mn0), p1 = __expf(s[1] - mn0);
            float p2 = __expf(s[2] - mn1), p3 = __expf(s[3] - mn1);
            ps0 += p0 + p1; ps1 += p2 + p3;
            unsigned h01 = pack_bf16x2(p0, p1);
            unsigned h23 = pack_bf16x2(p2, p3);
            __nv_bfloat162 hb01 = *(__nv_bfloat162*)&h01;
            __nv_bfloat162 hb23 = *(__nv_bfloat162*)&h23;
            unsigned lo01 = pack_bf16x2(p0 - __bfloat162float(hb01.x),
                                        p1 - __bfloat162float(hb01.y));
            unsigned lo23 = pack_bf16x2(p2 - __bfloat162float(hb23.x),
                                        p3 - __bfloat162float(hb23.y));
            int kc = nt >> 1, rlo = (nt & 1) * 2;
            pah[kc][rlo]     = h01;
            pah[kc][rlo + 1] = h23;
            pal[kc][rlo]     = lo01;
            pal[kc][rlo + 1] = lo23;
        }
        ps0 += __shfl_xor_sync(0xFFFFFFFFu, ps0, 1);
        ps0 += __shfl_xor_sync(0xFFFFFFFFu, ps0, 2);
        ps1 += __shfl_xor_sync(0xFFFFFFFFu, ps1, 1);
        ps1 += __shfl_xor_sync(0xFFFFFFFFu, ps1, 2);
        l0 = a0 * l0 + ps0;
        l1 = a1 * l1 + ps1;

        // ---- rescale O (registers) ----
#pragma unroll
        for (int nt = 0; nt < 8; nt++) {
            oacc[nt][0] *= a0; oacc[nt][1] *= a0;
            oacc[nt][2] *= a1; oacc[nt][3] *= a1;
        }

        // ---- O += P @ V ----
#pragma unroll
        for (int nt = 0; nt < 8; nt++) {
            const __nv_bfloat16* vbh = Vth + (nt * 8 + lrow) * 72 + lk;
            const __nv_bfloat16* vbl = Vtl + (nt * 8 + lrow) * 72 + lk;
#pragma unroll
            for (int kc = 0; kc < 4; kc++) {
                unsigned vh0 = *(const unsigned*)(vbh + kc * 16);
                unsigned vh1 = *(const unsigned*)(vbh + kc * 16 + 8);
                unsigned vl0 = *(const unsigned*)(vbl + kc * 16);
                unsigned vl1 = *(const unsigned*)(vbl + kc * 16 + 8);
                MMA_BF16(oacc[nt], pah[kc], vh0, vh1);
                MMA_BF16(oacc[nt], pah[kc], vl0, vl1);
                MMA_BF16(oacc[nt], pal[kc], vh0, vh1);
            }
        }
    }

    // ---- normalize + write y (bf16 hi/lo pairs) ----
    float i0 = 1.0f / l0, i1 = 1.0f / l1;
    size_t wb0 = (size_t)(b * TT + r0g) * 1024 + h * 64 + lk;
    size_t wb1 = wb0 + (size_t)8 * 1024;
#pragma unroll
    for (int nt = 0; nt < 8; nt++) {
        float v00 = oacc[nt][0] * i0, v01 = oacc[nt][1] * i0;
        float v10 = oacc[nt][2] * i1, v11 = oacc[nt][3] * i1;
        unsigned h0 = pack_bf16x2(v00, v01);
        __nv_bfloat162 hb0 = *(__nv_bfloat162*)&h0;
        unsigned lo0 = pack_bf16x2(v00 - __bfloat162float(hb0.x),
                                   v01 - __bfloat162float(hb0.y));
        unsigned h1 = pack_bf16x2(v10, v11);
        __nv_bfloat162 hb1 = *(__nv_bfloat162*)&h1;
        unsigned lo1 = pack_bf16x2(v10 - __bfloat162float(hb1.x),
                                   v11 - __bfloat162float(hb1.y));
        *(unsigned*)(g_yh + wb0 + nt * 8) = h0;
        *(unsigned*)(g_yl + wb0 + nt * 8) = lo0;
        *(unsigned*)(g_yh + wb1 + nt * 8) = h1;
        *(unsigned*)(g_yl + wb1 + nt * 8) = lo1;
    }
}

// ---------------------------------------------------------------------------
// kernel_launch
// ---------------------------------------------------------------------------
extern "C" void kernel_launch(void* const* d_in, const int* in_sizes, int n_in,
                              void* d_out, int out_size)
{
    const float* x  = (const float*)d_in[0];
    const float* Wa = (const float*)d_in[2];
    const float* ba = (const float*)d_in[3];
    const float* Wp = (const float*)d_in[4];
    const float* bp = (const float*)d_in[5];
    float* out = (float*)d_out;

    void *xh, *xl, *Wah, *Wal, *Wph, *Wpl, *qh, *ql, *yh, *yl;
    cudaGetSymbolAddress(&xh, g_xh);   cudaGetSymbolAddress(&xl, g_xl);
    cudaGetSymbolAddress(&Wah, g_Wah); cudaGetSymbolAddress(&Wal, g_Wal);
    cudaGetSymbolAddress(&Wph, g_Wph); cudaGetSymbolAddress(&Wpl, g_Wpl);
    cudaGetSymbolAddress(&qh, g_qh);   cudaGetSymbolAddress(&ql, g_ql);
    cudaGetSymbolAddress(&yh, g_yh);   cudaGetSymbolAddress(&yl, g_yl);

    cudaFuncSetAttribute((const void*)gemm_kernel,
                         cudaFuncAttributeMaxDynamicSharedMemorySize, 75776);
    cudaFuncSetAttribute((const void*)attn_kernel,
                         cudaFuncAttributeMaxDynamicSharedMemorySize, 92160);

    split_kernel<<<8192, 256>>>((const float4*)x,  (__nv_bfloat16*)xh,  (__nv_bfloat16*)xl,  8192 * 1024 / 4);
    split_kernel<<<3072, 256>>>((const float4*)Wa, (__nv_bfloat16*)Wah, (__nv_bfloat16*)Wal, 1024 * 3072 / 4);
    split_kernel<<<1024, 256>>>((const float4*)Wp, (__nv_bfloat16*)Wph, (__nv_bfloat16*)Wpl, 1024 * 1024 / 4);

    // qkv = x @ W_attn + b_attn  -> bf16 hi/lo
    gemm_kernel<<<dim3(3072 / 128, 8192 / 128), 256, 75776>>>(
        (const __nv_bfloat16*)xh, (const __nv_bfloat16*)xl,
        (const __nv_bfloat16*)Wah, (const __nv_bfloat16*)Wal,
        ba, nullptr, (__nv_bfloat16*)qh, (__nv_bfloat16*)ql,
        8192, 3072, 1024);

    // y = causal MHA(qkv) -> bf16 hi/lo
    attn_kernel<<<dim3(TT / 128, TB * TH), 256, 92160>>>();

    // out = y @ W_proj + b_proj -> fp32
    gemm_kernel<<<dim3(1024 / 128, 8192 / 128), 256, 75776>>>(
        (const __nv_bfloat16*)yh, (const __nv_bfloat16*)yl,
        (const __nv_bfloat16*)Wph, (const __nv_bfloat16*)Wpl,
        bp, out, nullptr, nullptr,
        8192, 1024, 1024);
}

// round 11
// speedup vs baseline: 1.5626x; 1.1018x over previous
#include <cstdint>
#include <cuda_runtime.h>
#include <cuda_bf16.h>
#include <mma.h>

using namespace nvcuda;

#define TB 4
#define TT 2048

static __device__ __nv_bfloat16 g_xh[8192 * 1024], g_xl[8192 * 1024];
static __device__ __nv_bfloat16 g_Wah[1024 * 3072], g_Wal[1024 * 3072]; // [K][N]
static __device__ __nv_bfloat16 g_Wph[1024 * 1024], g_Wpl[1024 * 1024]; // [K][N]
static __device__ __nv_bfloat16 g_qh[8192 * 3072], g_ql[8192 * 3072];
static __device__ __nv_bfloat16 g_yh[8192 * 1024], g_yl[8192 * 1024];

__device__ __forceinline__ void split_bf16(float x, __nv_bfloat16& hi, __nv_bfloat16& lo) {
    hi = __float2bfloat16(x);
    lo = __float2bfloat16(x - __bfloat162float(hi));
}

__device__ __forceinline__ unsigned pack_bf16x2(float e0, float e1) {
    __nv_bfloat162 t = __floats2bfloat162_rn(e0, e1);
    unsigned r;
    *(__nv_bfloat162*)&r = t;
    return r;
}

__device__ __forceinline__ void cp16(void* sptr, const void* gptr) {
    unsigned s = (unsigned)__cvta_generic_to_shared(sptr);
    asm volatile("cp.async.cg.shared.global [%0], [%1], 16;\n" :: "r"(s), "l"(gptr));
}
__device__ __forceinline__ void cp_commit() {
    asm volatile("cp.async.commit_group;\n");
}
template <int NN> __device__ __forceinline__ void cp_wait() {
    asm volatile("cp.async.wait_group %0;\n" :: "n"(NN));
}

__device__ __forceinline__ unsigned smem_u32(const void* p) {
    return (unsigned)__cvta_generic_to_shared(p);
}

// ldmatrix x4, non-transposed / transposed
__device__ __forceinline__ void ldsm4(unsigned& r0, unsigned& r1, unsigned& r2,
                                      unsigned& r3, unsigned addr) {
    asm volatile("ldmatrix.sync.aligned.m8n8.x4.shared.b16 {%0,%1,%2,%3}, [%4];"
                 : "=r"(r0), "=r"(r1), "=r"(r2), "=r"(r3) : "r"(addr));
}
__device__ __forceinline__ void ldsm4t(unsigned& r0, unsigned& r1, unsigned& r2,
                                       unsigned& r3, unsigned addr) {
    asm volatile("ldmatrix.sync.aligned.m8n8.x4.trans.shared.b16 {%0,%1,%2,%3}, [%4];"
                 : "=r"(r0), "=r"(r1), "=r"(r2), "=r"(r3) : "r"(addr));
}

#define MMA_BF16(d, a, b0_, b1_)                                                  \
    asm volatile(                                                                 \
        "mma.sync.aligned.m16n8k16.row.col.f32.bf16.bf16.f32 "                    \
        "{%0,%1,%2,%3}, {%4,%5,%6,%7}, {%8,%9}, {%0,%1,%2,%3};\n"                 \
        : "+f"((d)[0]), "+f"((d)[1]), "+f"((d)[2]), "+f"((d)[3])                  \
        : "r"((a)[0]), "r"((a)[1]), "r"((a)[2]), "r"((a)[3]), "r"(b0_), "r"(b1_))

__global__ __launch_bounds__(256) void split_kernel(
    const float4* __restrict__ src, __nv_bfloat16* __restrict__ hi,
    __nv_bfloat16* __restrict__ lo, int n4)
{
    int i = blockIdx.x * blockDim.x + threadIdx.x;
    if (i >= n4) return;
    float4 v = src[i];
    float f[4] = {v.x, v.y, v.z, v.w};
    __nv_bfloat16 h[4], l[4];
#pragma unroll
    for (int j = 0; j < 4; j++) split_bf16(f[j], h[j], l[j]);
    *(uint2*)(hi + i * 4) = *(uint2*)h;
    *(uint2*)(lo + i * 4) = *(uint2*)l;
}

// ---------------------------------------------------------------------------
// GEMM: C[M,N] = Ahl[M,K] @ Bhl[K,N] + bias   (3-term bf16, wmma)
// Tile 128x128, BK=32, 256 thr, warp tile 32x64. cp.async double-buffer.
// One __syncthreads per K-iter.
// ---------------------------------------------------------------------------
__global__ __launch_bounds__(256, 2) void gemm_kernel(
    const __nv_bfloat16* __restrict__ Ah_g, const __nv_bfloat16* __restrict__ Al_g,
    const __nv_bfloat16* __restrict__ Bh_g, const __nv_bfloat16* __restrict__ Bl_g,
    const float* __restrict__ bias,
    float* __restrict__ Cf, __nv_bfloat16* __restrict__ Chi, __nv_bfloat16* __restrict__ Clo,
    int M, int N, int K)
{
    extern __shared__ __align__(16) char sm[];
    __nv_bfloat16* Ah = (__nv_bfloat16*)sm;      // [2][128*40]
    __nv_bfloat16* Al = Ah + 2 * 5120;
    __nv_bfloat16* Bh = Al + 2 * 5120;           // [2][32*136]
    __nv_bfloat16* Bl = Bh + 2 * 4352;

    const int tid = threadIdx.x;
    const int wid = tid >> 5;
    const int lane = tid & 31;
    const int warp_row = wid >> 1;
    const int warp_col = wid & 1;
    const int bm = blockIdx.y * 128;
    const int bn = blockIdx.x * 128;

    wmma::fragment<wmma::accumulator, 16, 16, 16, float> acc[2][4];
#pragma unroll
    for (int mm = 0; mm < 2; mm++)
#pragma unroll
        for (int nn = 0; nn < 4; nn++) wmma::fill_fragment(acc[mm][nn], 0.0f);

#define GEMM_PREFETCH(KT, ST)                                                        \
    {                                                                                \
        int k0 = (KT) * 32;                                                          \
        _Pragma("unroll")                                                            \
        for (int jj = 0; jj < 2; jj++) {                                             \
            int idx = tid * 2 + jj;                                                  \
            int row = idx >> 2, ch = idx & 3;                                        \
            size_t g = (size_t)(bm + row) * K + k0 + ch * 8;                         \
            cp16(&Ah[(ST) * 5120 + row * 40 + ch * 8], Ah_g + g);                    \
            cp16(&Al[(ST) * 5120 + row * 40 + ch * 8], Al_g + g);                    \
        }                                                                            \
        _Pragma("unroll")                                                            \
        for (int jj = 0; jj < 2; jj++) {                                             \
            int idx = tid * 2 + jj;                                                  \
            int row = idx >> 4, ch = idx & 15;                                       \
            size_t g = (size_t)(k0 + row) * N + bn + ch * 8;                         \
            cp16(&Bh[(ST) * 4352 + row * 136 + ch * 8], Bh_g + g);                   \
            cp16(&Bl[(ST) * 4352 + row * 136 + ch * 8], Bl_g + g);                   \
        }                                                                            \
        cp_commit();                                                                 \
    }

    GEMM_PREFETCH(0, 0);

    const int NK = K >> 5;
    for (int kt = 0; kt < NK; kt++) {
        cp_wait<0>();
        __syncthreads();
        if (kt + 1 < NK) { GEMM_PREFETCH(kt + 1, (kt + 1) & 1); }

        const int st = kt & 1;
        const __nv_bfloat16* Ahc = Ah + st * 5120;
        const __nv_bfloat16* Alc = Al + st * 5120;
        const __nv_bfloat16* Bhc = Bh + st * 4352;
        const __nv_bfloat16* Blc = Bl + st * 4352;

#pragma unroll
        for (int ks = 0; ks < 2; ks++) {
            const int kk = ks * 16;
            wmma::fragment<wmma::matrix_a, 16, 16, 16, __nv_bfloat16, wmma::row_major> ah[2], al[2];
#pragma unroll
            for (int mm = 0; mm < 2; mm++) {
                wmma::load_matrix_sync(ah[mm], Ahc + (warp_row * 32 + mm * 16) * 40 + kk, 40);
                wmma::load_matrix_sync(al[mm], Alc + (warp_row * 32 + mm * 16) * 40 + kk, 40);
            }
#pragma unroll
            for (int nn = 0; nn < 4; nn++) {
                wmma::fragment<wmma::matrix_b, 16, 16, 16, __nv_bfloat16, wmma::row_major> bh, bl;
                wmma::load_matrix_sync(bh, Bhc + kk * 136 + warp_col * 64 + nn * 16, 136);
                wmma::load_matrix_sync(bl, Blc + kk * 136 + warp_col * 64 + nn * 16, 136);
#pragma unroll
                for (int mm = 0; mm < 2; mm++) {
                    wmma::mma_sync(acc[mm][nn], ah[mm], bh, acc[mm][nn]);
                    wmma::mma_sync(acc[mm][nn], ah[mm], bl, acc[mm][nn]);
                    wmma::mma_sync(acc[mm][nn], al[mm], bh, acc[mm][nn]);
                }
            }
        }
    }
    __syncthreads();  // before reusing smem as epilogue patch

    float* patch = (float*)sm + wid * 1152;
    const int crow = bm + warp_row * 32;
#pragma unroll
    for (int hh = 0; hh < 2; hh++) {
        wmma::store_matrix_sync(patch, acc[0][2 * hh], 36, wmma::mem_row_major);
        wmma::store_matrix_sync(patch + 16, acc[0][2 * hh + 1], 36, wmma::mem_row_major);
        wmma::store_matrix_sync(patch + 16 * 36, acc[1][2 * hh], 36, wmma::mem_row_major);
        wmma::store_matrix_sync(patch + 16 * 36 + 16, acc[1][2 * hh + 1], 36, wmma::mem_row_major);
        __syncwarp();
        const int ccol = bn + warp_col * 64 + hh * 32;
        for (int i = lane; i < 1024; i += 32) {
            int r = i >> 5, c = i & 31;
            float val = patch[r * 36 + c] + bias[ccol + c];
            size_t idx = (size_t)(crow + r) * N + ccol + c;
            if (Chi) {
                __nv_bfloat16 hi, lo;
                split_bf16(val, hi, lo);
                Chi[idx] = hi;
                Clo[idx] = lo;
            } else {
                Cf[idx] = val;
            }
        }
        __syncwarp();
    }
}

// ---------------------------------------------------------------------------
// Flash attention (causal), register-resident, ldmatrix K/V fragments.
// Block = 128 query rows x one (b,h); 8 warps x 16 rows; KV tiles of 64.
// ---------------------------------------------------------------------------
__global__ __launch_bounds__(256, 1) void attn_kernel()
{
    extern __shared__ __align__(16) char sm[];
    // Kh[2][64*72], Kl, Vh[2][64*72], Vl (bf16): 73728 bytes total
    __nv_bfloat16* Kh = (__nv_bfloat16*)sm;
    __nv_bfloat16* Kl = Kh + 2 * 4608;
    __nv_bfloat16* Vh = Kl + 2 * 4608;
    __nv_bfloat16* Vl = Vh + 2 * 4608;

    const int tid = threadIdx.x;
    const int wid = tid >> 5;
    const int lane = tid & 31;
    const int qt = (gridDim.x - 1) - blockIdx.x;   // heavy tiles first
    const int qs = qt * 128;
    const int bh = blockIdx.y;
    const int b = bh >> 4, h = bh & 15;
    const int wrow = wid * 16;

    const int lrow = lane >> 2;
    const int lk   = (lane & 3) * 2;

    const unsigned Kh_u = smem_u32(Kh);
    const unsigned Kl_u = smem_u32(Kl);
    const unsigned Vh_u = smem_u32(Vh);
    const unsigned Vl_u = smem_u32(Vl);
    // ldmatrix per-lane offsets (bytes), row stride 144B
    const unsigned laneK = (unsigned)(((lane >> 4) * 8 + (lane & 7)) * 144 +
                                      ((lane >> 3) & 1) * 16);
    const unsigned laneV = (unsigned)((((lane >> 3) & 1) * 8 + (lane & 7)) * 144 +
                                      (lane >> 4) * 16);

#define ATTN_LOADKV(J, ST)                                                           \
    {                                                                                \
        size_t base = (size_t)(b * TT + (J) * 64) * 3072 + h * 64;                   \
        _Pragma("unroll")                                                            \
        for (int jj = 0; jj < 2; jj++) {                                             \
            int idx = tid * 2 + jj;                                                  \
            int row = idx >> 3, ch = idx & 7;                                        \
            size_t g = base + (size_t)row * 3072 + ch * 8;                           \
            cp16(&Kh[(ST) * 4608 + row * 72 + ch * 8], g_qh + 1024 + g);             \
            cp16(&Kl[(ST) * 4608 + row * 72 + ch * 8], g_ql + 1024 + g);             \
            cp16(&Vh[(ST) * 4608 + row * 72 + ch * 8], g_qh + 2048 + g);             \
            cp16(&Vl[(ST) * 4608 + row * 72 + ch * 8], g_ql + 2048 + g);             \
        }                                                                            \
        cp_commit();                                                                 \
    }

    ATTN_LOADKV(0, 0);

    // Q fragments from gmem (one-time)
    unsigned qhf[4][4], qlf[4][4];
    {
        const int r0 = qs + wrow + lrow;
        size_t base0 = (size_t)(b * TT + r0) * 3072 + h * 64;
        size_t base1 = base0 + (size_t)8 * 3072;
#pragma unroll
        for (int kc = 0; kc < 4; kc++) {
            int k0 = kc * 16 + lk;
            qhf[kc][0] = *(const unsigned*)(g_qh + base0 + k0);
            qhf[kc][1] = *(const unsigned*)(g_qh + base1 + k0);
            qhf[kc][2] = *(const unsigned*)(g_qh + base0 + k0 + 8);
            qhf[kc][3] = *(const unsigned*)(g_qh + base1 + k0 + 8);
            qlf[kc][0] = *(const unsigned*)(g_ql + base0 + k0);
            qlf[kc][1] = *(const unsigned*)(g_ql + base1 + k0);
            qlf[kc][2] = *(const unsigned*)(g_ql + base0 + k0 + 8);
            qlf[kc][3] = *(const unsigned*)(g_ql + base1 + k0 + 8);
        }
    }

    float oacc[8][4];
#pragma unroll
    for (int nt = 0; nt < 8; nt++)
#pragma unroll
        for (int e = 0; e < 4; e++) oacc[nt][e] = 0.0f;
    float m0 = -1e30f, m1 = -1e30f, l0 = 0.0f, l1 = 0.0f;

    const int r0g = qs + wrow + lrow;
    const int r1g = r0g + 8;
    const int jmax = 2 * qt + 1;

    for (int j = 0; j <= jmax; j++) {
        cp_wait<0>();
        __syncthreads();
        const int st = j & 1;
        if (j < jmax) { ATTN_LOADKV(j + 1, st ^ 1); }

        if (j * 64 > qs + wrow + 15) continue;  // whole warp masked

        // ---- S = Q @ K^T ----
        const unsigned khq = Kh_u + st * 9216u + laneK;
        const unsigned klq = Kl_u + st * 9216u + laneK;
        float sacc[8][4];
#pragma unroll
        for (int nt = 0; nt < 8; nt++)
            sacc[nt][0] = sacc[nt][1] = sacc[nt][2] = sacc[nt][3] = 0.0f;
#pragma unroll
        for (int nt2 = 0; nt2 < 4; nt2++) {
            float* s0 = sacc[2 * nt2];
            float* s1 = sacc[2 * nt2 + 1];
#pragma unroll
            for (int kc = 0; kc < 4; kc++) {
                unsigned h0, h1, h2, h3, e0, e1, e2, e3;
                ldsm4(h0, h1, h2, h3, khq + nt2 * 2304u + kc * 32u);
                ldsm4(e0, e1, e2, e3, klq + nt2 * 2304u + kc * 32u);
                MMA_BF16(s0, qhf[kc], h0, h1);
                MMA_BF16(s0, qhf[kc], e0, e1);
                MMA_BF16(s0, qlf[kc], h0, h1);
                MMA_BF16(s1, qhf[kc], h2, h3);
                MMA_BF16(s1, qhf[kc], e2, e3);
                MMA_BF16(s1, qlf[kc], h2, h3);
            }
        }

        // ---- softmax (registers) ----
        const bool needmask = (j * 64 + 63 > qs + wrow);
        float mt0 = -1e30f, mt1 = -1e30f;
#pragma unroll
        for (int nt = 0; nt < 8; nt++) {
            float* s = sacc[nt];
            s[0] *= 0.125f; s[1] *= 0.125f; s[2] *= 0.125f; s[3] *= 0.125f;
            if (needmask) {
                int c0 = j * 64 + nt * 8 + lk;
                if (c0     > r0g) s[0] = -1e30f;
                if (c0 + 1 > r0g) s[1] = -1e30f;
                if (c0     > r1g) s[2] = -1e30f;
                if (c0 + 1 > r1g) s[3] = -1e30f;
            }
            mt0 = fmaxf(mt0, fmaxf(s[0], s[1]));
            mt1 = fmaxf(mt1, fmaxf(s[2], s[3]));
        }
        mt0 = fmaxf(mt0, __shfl_xor_sync(0xFFFFFFFFu, mt0, 1));
        mt0 = fmaxf(mt0, __shfl_xor_sync(0xFFFFFFFFu, mt0, 2));
        mt1 = fmaxf(mt1, __shfl_xor_sync(0xFFFFFFFFu, mt1, 1));
        mt1 = fmaxf(mt1, __shfl_xor_sync(0xFFFFFFFFu, mt1, 2));
        float mn0 = fmaxf(m0, mt0), mn1 = fmaxf(m1, mt1);
        float a0 = __expf(m0 - mn0), a1 = __expf(m1 - mn1);
        m0 = mn0; m1 = mn1;

        float ps0 = 0.0f, ps1 = 0.0f;
        unsigned pah[4][4], pal[4][4];
#pragma unroll
        for (int nt = 0; nt < 8; nt++) {
            float* s = sacc[nt];
            float p0 = __expf(s[0] - mn0), p1 = __expf(s[1] - mn0);
            float p2 = __expf(s[2] - mn1), p3 = __expf(s[3] - mn1);
            ps0 += p0 + p1; ps1 += p2 + p3;
            unsigned h01 = pack_bf16x2(p0, p1);
            unsigned h23 = pack_bf16x2(p2, p3);
            __nv_bfloat162 hb01 = *(__nv_bfloat162*)&h01;
            __nv_bfloat162 hb23 = *(__nv_bfloat162*)&h23;
            unsigned lo01 = pack_bf16x2(p0 - __bfloat162float(hb01.x),
                                        p1 - __bfloat162float(hb01.y));
            unsigned lo23 = pack_bf16x2(p2 - __bfloat162float(hb23.x),
                                        p3 - __bfloat162float(hb23.y));
            int kc = nt >> 1, rlo = (nt & 1) * 2;
            pah[kc][rlo]     = h01;
            pah[kc][rlo + 1] = h23;
            pal[kc][rlo]     = lo01;
            pal[kc][rlo + 1] = lo23;
        }
        ps0 += __shfl_xor_sync(0xFFFFFFFFu, ps0, 1);
        ps0 += __shfl_xor_sync(0xFFFFFFFFu, ps0, 2);
        ps1 += __shfl_xor_sync(0xFFFFFFFFu, ps1, 1);
        ps1 += __shfl_xor_sync(0xFFFFFFFFu, ps1, 2);
        l0 = a0 * l0 + ps0;
        l1 = a1 * l1 + ps1;

#pragma unroll
        for (int nt = 0; nt < 8; nt++) {
            oacc[nt][0] *= a0; oacc[nt][1] *= a0;
            oacc[nt][2] *= a1; oacc[nt][3] *= a1;
        }

        // ---- O += P @ V (ldmatrix.trans on row-major V) ----
        const unsigned vhq = Vh_u + st * 9216u + laneV;
        const unsigned vlq = Vl_u + st * 9216u + laneV;
#pragma unroll
        for (int kc = 0; kc < 4; kc++) {
#pragma unroll
            for (int nt2 = 0; nt2 < 4; nt2++) {
                unsigned h0, h1, h2, h3, e0, e1, e2, e3;
                ldsm4t(h0, h1, h2, h3, vhq + kc * 2304u + nt2 * 32u);
                ldsm4t(e0, e1, e2, e3, vlq + kc * 2304u + nt2 * 32u);
                float* o0 = oacc[2 * nt2];
                float* o1 = oacc[2 * nt2 + 1];
                MMA_BF16(o0, pah[kc], h0, h1);
                MMA_BF16(o0, pah[kc], e0, e1);
                MMA_BF16(o0, pal[kc], h0, h1);
                MMA_BF16(o1, pah[kc], h2, h3);
                MMA_BF16(o1, pah[kc], e2, e3);
                MMA_BF16(o1, pal[kc], h2, h3);
            }
        }
    }

    // ---- normalize + write y (bf16 hi/lo pairs) ----
    float i0 = 1.0f / l0, i1 = 1.0f / l1;
    size_t wb0 = (size_t)(b * TT + r0g) * 1024 + h * 64 + lk;
    size_t wb1 = wb0 + (size_t)8 * 1024;
#pragma unroll
    for (int nt = 0; nt < 8; nt++) {
        float v00 = oacc[nt][0] * i0, v01 = oacc[nt][1] * i0;
        float v10 = oacc[nt][2] * i1, v11 = oacc[nt][3] * i1;
        unsigned h0 = pack_bf16x2(v00, v01);
        __nv_bfloat162 hb0 = *(__nv_bfloat162*)&h0;
        unsigned lo0 = pack_bf16x2(v00 - __bfloat162float(hb0.x),
                                   v01 - __bfloat162float(hb0.y));
        unsigned h1 = pack_bf16x2(v10, v11);
        __nv_bfloat162 hb1 = *(__nv_bfloat162*)&h1;
        unsigned lo1 = pack_bf16x2(v10 - __bfloat162float(hb1.x),
                                   v11 - __bfloat162float(hb1.y));
        *(unsigned*)(g_yh + wb0 + nt * 8) = h0;
        *(unsigned*)(g_yl + wb0 + nt * 8) = lo0;
        *(unsigned*)(g_yh + wb1 + nt * 8) = h1;
        *(unsigned*)(g_yl + wb1 + nt * 8) = lo1;
    }
}

extern "C" void kernel_launch(void* const* d_in, const int* in_sizes, int n_in,
                              void* d_out, int out_size)
{
    const float* x  = (const float*)d_in[0];
    const float* Wa = (const float*)d_in[2];
    const float* ba = (const float*)d_in[3];
    const float* Wp = (const float*)d_in[4];
    const float* bp = (const float*)d_in[5];
    float* out = (float*)d_out;

    void *xh, *xl, *Wah, *Wal, *Wph, *Wpl, *qh, *ql, *yh, *yl;
    cudaGetSymbolAddress(&xh, g_xh);   cudaGetSymbolAddress(&xl, g_xl);
    cudaGetSymbolAddress(&Wah, g_Wah); cudaGetSymbolAddress(&Wal, g_Wal);
    cudaGetSymbolAddress(&Wph, g_Wph); cudaGetSymbolAddress(&Wpl, g_Wpl);
    cudaGetSymbolAddress(&qh, g_qh);   cudaGetSymbolAddress(&ql, g_ql);
    cudaGetSymbolAddress(&yh, g_yh);   cudaGetSymbolAddress(&yl, g_yl);

    cudaFuncSetAttribute((const void*)gemm_kernel,
                         cudaFuncAttributeMaxDynamicSharedMemorySize, 75776);
    cudaFuncSetAttribute((const void*)attn_kernel,
                         cudaFuncAttributeMaxDynamicSharedMemorySize, 73728);

    split_kernel<<<8192, 256>>>((const float4*)x,  (__nv_bfloat16*)xh,  (__nv_bfloat16*)xl,  8192 * 1024 / 4);
    split_kernel<<<3072, 256>>>((const float4*)Wa, (__nv_bfloat16*)Wah, (__nv_bfloat16*)Wal, 1024 * 3072 / 4);
    split_kernel<<<1024, 256>>>((const float4*)Wp, (__nv_bfloat16*)Wph, (__nv_bfloat16*)Wpl, 1024 * 1024 / 4);

    gemm_kernel<<<dim3(3072 / 128, 8192 / 128), 256, 75776>>>(
        (const __nv_bfloat16*)xh, (const __nv_bfloat16*)xl,
        (const __nv_bfloat16*)Wah, (const __nv_bfloat16*)Wal,
        ba, nullptr, (__nv_bfloat16*)qh, (__nv_bfloat16*)ql,
        8192, 3072, 1024);

    attn_kernel<<<dim3(TT / 128, 64), 256, 73728>>>();

    gemm_kernel<<<dim3(1024 / 128, 8192 / 128), 256, 75776>>>(
        (const __nv_bfloat16*)yh, (const __nv_bfloat16*)yl,
        (const __nv_bfloat16*)Wph, (const __nv_bfloat16*)Wpl,
        bp, out, nullptr, nullptr,
        8192, 1024, 1024);
}

// round 12
// speedup vs baseline: 1.8611x; 1.1911x over previous
#include <cstdint>
#include <cuda_runtime.h>
#include <cuda_bf16.h>

#define TB 4
#define TT 2048

static __device__ __nv_bfloat16 g_xh[8192 * 1024], g_xl[8192 * 1024];
static __device__ __nv_bfloat16 g_Wah[1024 * 3072], g_Wal[1024 * 3072]; // [K][N]
static __device__ __nv_bfloat16 g_Wph[1024 * 1024], g_Wpl[1024 * 1024]; // [K][N]
static __device__ __nv_bfloat16 g_qh[8192 * 3072], g_ql[8192 * 3072];
static __device__ __nv_bfloat16 g_yh[8192 * 1024], g_yl[8192 * 1024];

__device__ __forceinline__ void split_bf16(float x, __nv_bfloat16& hi, __nv_bfloat16& lo) {
    hi = __float2bfloat16(x);
    lo = __float2bfloat16(x - __bfloat162float(hi));
}

__device__ __forceinline__ unsigned pack_bf16x2(float e0, float e1) {
    __nv_bfloat162 t = __floats2bfloat162_rn(e0, e1);
    unsigned r;
    *(__nv_bfloat162*)&r = t;
    return r;
}

__device__ __forceinline__ void cp16(void* sptr, const void* gptr) {
    unsigned s = (unsigned)__cvta_generic_to_shared(sptr);
    asm volatile("cp.async.cg.shared.global [%0], [%1], 16;\n" :: "r"(s), "l"(gptr));
}
__device__ __forceinline__ void cp_commit() {
    asm volatile("cp.async.commit_group;\n");
}
template <int NN> __device__ __forceinline__ void cp_wait() {
    asm volatile("cp.async.wait_group %0;\n" :: "n"(NN));
}

__device__ __forceinline__ unsigned smem_u32(const void* p) {
    return (unsigned)__cvta_generic_to_shared(p);
}

__device__ __forceinline__ void ldsm4(unsigned& r0, unsigned& r1, unsigned& r2,
                                      unsigned& r3, unsigned addr) {
    asm volatile("ldmatrix.sync.aligned.m8n8.x4.shared.b16 {%0,%1,%2,%3}, [%4];"
                 : "=r"(r0), "=r"(r1), "=r"(r2), "=r"(r3) : "r"(addr));
}
__device__ __forceinline__ void ldsm4t(unsigned& r0, unsigned& r1, unsigned& r2,
                                       unsigned& r3, unsigned addr) {
    asm volatile("ldmatrix.sync.aligned.m8n8.x4.trans.shared.b16 {%0,%1,%2,%3}, [%4];"
                 : "=r"(r0), "=r"(r1), "=r"(r2), "=r"(r3) : "r"(addr));
}

#define MMA_BF16(d, a, b0_, b1_)                                                  \
    asm volatile(                                                                 \
        "mma.sync.aligned.m16n8k16.row.col.f32.bf16.bf16.f32 "                    \
        "{%0,%1,%2,%3}, {%4,%5,%6,%7}, {%8,%9}, {%0,%1,%2,%3};\n"                 \
        : "+f"((d)[0]), "+f"((d)[1]), "+f"((d)[2]), "+f"((d)[3])                  \
        : "r"((a)[0]), "r"((a)[1]), "r"((a)[2]), "r"((a)[3]), "r"(b0_), "r"(b1_))

__global__ __launch_bounds__(256) void split_kernel(
    const float4* __restrict__ src, __nv_bfloat16* __restrict__ hi,
    __nv_bfloat16* __restrict__ lo, int n4)
{
    int i = blockIdx.x * blockDim.x + threadIdx.x;
    if (i >= n4) return;
    float4 v = src[i];
    float f[4] = {v.x, v.y, v.z, v.w};
    __nv_bfloat16 h[4], l[4];
#pragma unroll
    for (int j = 0; j < 4; j++) split_bf16(f[j], h[j], l[j]);
    *(uint2*)(hi + i * 4) = *(uint2*)h;
    *(uint2*)(lo + i * 4) = *(uint2*)l;
}

// ---------------------------------------------------------------------------
// GEMM: C[M,N] = Ahl[M,K] @ Bhl[K,N] + bias   (3-term bf16, raw mma+ldmatrix)
// Tile 128x128, BK=32, 256 thr, warp tile 32x64. cp.async double-buffer.
// Direct-to-gmem epilogue from known mma accumulator layout.
// ---------------------------------------------------------------------------
__global__ __launch_bounds__(256, 2) void gemm_kernel(
    const __nv_bfloat16* __restrict__ Ah_g, const __nv_bfloat16* __restrict__ Al_g,
    const __nv_bfloat16* __restrict__ Bh_g, const __nv_bfloat16* __restrict__ Bl_g,
    const float* __restrict__ bias,
    float* __restrict__ Cf, __nv_bfloat16* __restrict__ Chi, __nv_bfloat16* __restrict__ Clo,
    int M, int N, int K)
{
    extern __shared__ __align__(16) char sm[];
    __nv_bfloat16* Ah = (__nv_bfloat16*)sm;      // [2][128*40] bf16
    __nv_bfloat16* Al = Ah + 2 * 5120;
    __nv_bfloat16* Bh = Al + 2 * 5120;           // [2][32*136] bf16
    __nv_bfloat16* Bl = Bh + 2 * 4352;

    const int tid = threadIdx.x;
    const int wid = tid >> 5;
    const int lane = tid & 31;
    const int wr = wid >> 1;        // 0..3 -> 32 rows
    const int wc = wid & 1;         // 0..1 -> 64 cols
    const int bm = blockIdx.y * 128;
    const int bn = blockIdx.x * 128;

    const unsigned Ah_u = smem_u32(Ah);
    const unsigned Al_u = smem_u32(Al);
    const unsigned Bh_u = smem_u32(Bh);
    const unsigned Bl_u = smem_u32(Bl);

    // ldmatrix per-lane offsets (bytes). A stride 80B, B stride 272B.
    const unsigned laneA = (unsigned)((lane & 15) * 80 + (lane >> 4) * 16);
    const unsigned laneB = (unsigned)((((lane >> 3) & 1) * 8 + (lane & 7)) * 272 +
                                      (lane >> 4) * 16);

    float acc[2][8][4];
#pragma unroll
    for (int mt = 0; mt < 2; mt++)
#pragma unroll
        for (int nt = 0; nt < 8; nt++)
#pragma unroll
            for (int e = 0; e < 4; e++) acc[mt][nt][e] = 0.0f;

#define GEMM_PREFETCH(KT, ST)                                                        \
    {                                                                                \
        int k0 = (KT) * 32;                                                          \
        _Pragma("unroll")                                                            \
        for (int jj = 0; jj < 2; jj++) {                                             \
            int idx = tid * 2 + jj;                                                  \
            int row = idx >> 2, ch = idx & 3;                                        \
            size_t g = (size_t)(bm + row) * K + k0 + ch * 8;                         \
            cp16(&Ah[(ST) * 5120 + row * 40 + ch * 8], Ah_g + g);                    \
            cp16(&Al[(ST) * 5120 + row * 40 + ch * 8], Al_g + g);                    \
        }                                                                            \
        _Pragma("unroll")                                                            \
        for (int jj = 0; jj < 2; jj++) {                                             \
            int idx = tid * 2 + jj;                                                  \
            int row = idx >> 4, ch = idx & 15;                                       \
            size_t g = (size_t)(k0 + row) * N + bn + ch * 8;                         \
            cp16(&Bh[(ST) * 4352 + row * 136 + ch * 8], Bh_g + g);                   \
            cp16(&Bl[(ST) * 4352 + row * 136 + ch * 8], Bl_g + g);                   \
        }                                                                            \
        cp_commit();                                                                 \
    }

    GEMM_PREFETCH(0, 0);

    const int NK = K >> 5;
    for (int kt = 0; kt < NK; kt++) {
        cp_wait<0>();
        __syncthreads();
        if (kt + 1 < NK) { GEMM_PREFETCH(kt + 1, (kt + 1) & 1); }

        const int st = kt & 1;
        const unsigned a_warp = (unsigned)(st * 10240 + wr * 32 * 80) + laneA;
        const unsigned b_warp = (unsigned)(st * 8704 + wc * 128) + laneB;

#pragma unroll
        for (int ks = 0; ks < 2; ks++) {
            // A fragments: 2 m-tiles, hi+lo
            unsigned ahf[2][4], alf[2][4];
            const unsigned a_base = a_warp + (unsigned)(ks * 32);
#pragma unroll
            for (int mt = 0; mt < 2; mt++) {
                ldsm4(ahf[mt][0], ahf[mt][1], ahf[mt][2], ahf[mt][3],
                      Ah_u + a_base + mt * (16 * 80));
                ldsm4(alf[mt][0], alf[mt][1], alf[mt][2], alf[mt][3],
                      Al_u + a_base + mt * (16 * 80));
            }
            const unsigned b_base = b_warp + (unsigned)(ks * 16 * 272);
#pragma unroll
            for (int g = 0; g < 4; g++) {
                unsigned h0, h1, h2, h3, e0, e1, e2, e3;
                ldsm4t(h0, h1, h2, h3, Bh_u + b_base + g * 32);
                ldsm4t(e0, e1, e2, e3, Bl_u + b_base + g * 32);
#pragma unroll
                for (int mt = 0; mt < 2; mt++) {
                    float* c0 = acc[mt][2 * g];
                    float* c1 = acc[mt][2 * g + 1];
                    MMA_BF16(c0, ahf[mt], h0, h1);
                    MMA_BF16(c0, ahf[mt], e0, e1);
                    MMA_BF16(c0, alf[mt], h0, h1);
                    MMA_BF16(c1, ahf[mt], h2, h3);
                    MMA_BF16(c1, ahf[mt], e2, e3);
                    MMA_BF16(c1, alf[mt], h2, h3);
                }
            }
        }
    }

    // ---- direct-to-gmem epilogue (acc layout: rows lrow/+8, cols 2j/2j+1) ----
    const int lrow = lane >> 2;
    const int lk2 = (lane & 3) * 2;
#pragma unroll
    for (int mt = 0; mt < 2; mt++) {
        const int row0 = bm + wr * 32 + mt * 16 + lrow;
#pragma unroll
        for (int nt = 0; nt < 8; nt++) {
            const int col = bn + wc * 64 + nt * 8 + lk2;
            const float b0 = bias[col], b1 = bias[col + 1];
            float v00 = acc[mt][nt][0] + b0, v01 = acc[mt][nt][1] + b1;
            float v10 = acc[mt][nt][2] + b0, v11 = acc[mt][nt][3] + b1;
            size_t i0 = (size_t)row0 * N + col;
            size_t i1 = i0 + (size_t)8 * N;
            if (Chi) {
                unsigned h0 = pack_bf16x2(v00, v01);
                __nv_bfloat162 hb0 = *(__nv_bfloat162*)&h0;
                unsigned l0 = pack_bf16x2(v00 - __bfloat162float(hb0.x),
                                          v01 - __bfloat162float(hb0.y));
                unsigned h1 = pack_bf16x2(v10, v11);
                __nv_bfloat162 hb1 = *(__nv_bfloat162*)&h1;
                unsigned l1 = pack_bf16x2(v10 - __bfloat162float(hb1.x),
                                          v11 - __bfloat162float(hb1.y));
                *(unsigned*)(Chi + i0) = h0;
                *(unsigned*)(Clo + i0) = l0;
                *(unsigned*)(Chi + i1) = h1;
                *(unsigned*)(Clo + i1) = l1;
            } else {
                float2 f0; f0.x = v00; f0.y = v01;
                float2 f1; f1.x = v10; f1.y = v11;
                *(float2*)(Cf + i0) = f0;
                *(float2*)(Cf + i1) = f1;
            }
        }
    }
}

// ---------------------------------------------------------------------------
// Flash attention (causal), register-resident, ldmatrix K/V fragments.
// (R10 winner, unchanged.)
// ---------------------------------------------------------------------------
__global__ __launch_bounds__(256, 1) void attn_kernel()
{
    extern __shared__ __align__(16) char sm[];
    __nv_bfloat16* Kh = (__nv_bfloat16*)sm;
    __nv_bfloat16* Kl = Kh + 2 * 4608;
    __nv_bfloat16* Vh = Kl + 2 * 4608;
    __nv_bfloat16* Vl = Vh + 2 * 4608;

    const int tid = threadIdx.x;
    const int wid = tid >> 5;
    const int lane = tid & 31;
    const int qt = (gridDim.x - 1) - blockIdx.x;
    const int qs = qt * 128;
    const int bh = blockIdx.y;
    const int b = bh >> 4, h = bh & 15;
    const int wrow = wid * 16;

    const int lrow = lane >> 2;
    const int lk   = (lane & 3) * 2;

    const unsigned Kh_u = smem_u32(Kh);
    const unsigned Kl_u = smem_u32(Kl);
    const unsigned Vh_u = smem_u32(Vh);
    const unsigned Vl_u = smem_u32(Vl);
    const unsigned laneK = (unsigned)(((lane >> 4) * 8 + (lane & 7)) * 144 +
                                      ((lane >> 3) & 1) * 16);
    const unsigned laneV = (unsigned)((((lane >> 3) & 1) * 8 + (lane & 7)) * 144 +
                                      (lane >> 4) * 16);

#define ATTN_LOADKV(J, ST)                                                           \
    {                                                                                \
        size_t base = (size_t)(b * TT + (J) * 64) * 3072 + h * 64;                   \
        _Pragma("unroll")                                                            \
        for (int jj = 0; jj < 2; jj++) {                                             \
            int idx = tid * 2 + jj;                                                  \
            int row = idx >> 3, ch = idx & 7;                                        \
            size_t g = base + (size_t)row * 3072 + ch * 8;                           \
            cp16(&Kh[(ST) * 4608 + row * 72 + ch * 8], g_qh + 1024 + g);             \
            cp16(&Kl[(ST) * 4608 + row * 72 + ch * 8], g_ql + 1024 + g);             \
            cp16(&Vh[(ST) * 4608 + row * 72 + ch * 8], g_qh + 2048 + g);             \
            cp16(&Vl[(ST) * 4608 + row * 72 + ch * 8], g_ql + 2048 + g);             \
        }                                                                            \
        cp_commit();                                                                 \
    }

    ATTN_LOADKV(0, 0);

    unsigned qhf[4][4], qlf[4][4];
    {
        const int r0 = qs + wrow + lrow;
        size_t base0 = (size_t)(b * TT + r0) * 3072 + h * 64;
        size_t base1 = base0 + (size_t)8 * 3072;
#pragma unroll
        for (int kc = 0; kc < 4; kc++) {
            int k0 = kc * 16 + lk;
            qhf[kc][0] = *(const unsigned*)(g_qh + base0 + k0);
            qhf[kc][1] = *(const unsigned*)(g_qh + base1 + k0);
            qhf[kc][2] = *(const unsigned*)(g_qh + base0 + k0 + 8);
            qhf[kc][3] = *(const unsigned*)(g_qh + base1 + k0 + 8);
            qlf[kc][0] = *(const unsigned*)(g_ql + base0 + k0);
            qlf[kc][1] = *(const unsigned*)(g_ql + base1 + k0);
            qlf[kc][2] = *(const unsigned*)(g_ql + base0 + k0 + 8);
            qlf[kc][3] = *(const unsigned*)(g_ql + base1 + k0 + 8);
        }
    }

    float oacc[8][4];
#pragma unroll
    for (int nt = 0; nt < 8; nt++)
#pragma unroll
        for (int e = 0; e < 4; e++) oacc[nt][e] = 0.0f;
    float m0 = -1e30f, m1 = -1e30f, l0 = 0.0f, l1 = 0.0f;

    const int r0g = qs + wrow + lrow;
    const int r1g = r0g + 8;
    const int jmax = 2 * qt + 1;

    for (int j = 0; j <= jmax; j++) {
        cp_wait<0>();
        __syncthreads();
        const int st = j & 1;
        if (j < jmax) { ATTN_LOADKV(j + 1, st ^ 1); }

        if (j * 64 > qs + wrow + 15) continue;

        const unsigned khq = Kh_u + st * 9216u + laneK;
        const unsigned klq = Kl_u + st * 9216u + laneK;
        float sacc[8][4];
#pragma unroll
        for (int nt = 0; nt < 8; nt++)
            sacc[nt][0] = sacc[nt][1] = sacc[nt][2] = sacc[nt][3] = 0.0f;
#pragma unroll
        for (int nt2 = 0; nt2 < 4; nt2++) {
            float* s0 = sacc[2 * nt2];
            float* s1 = sacc[2 * nt2 + 1];
#pragma unroll
            for (int kc = 0; kc < 4; kc++) {
                unsigned h0, h1, h2, h3, e0, e1, e2, e3;
                ldsm4(h0, h1, h2, h3, khq + nt2 * 2304u + kc * 32u);
                ldsm4(e0, e1, e2, e3, klq + nt2 * 2304u + kc * 32u);
                MMA_BF16(s0, qhf[kc], h0, h1);
                MMA_BF16(s0, qhf[kc], e0, e1);
                MMA_BF16(s0, qlf[kc], h0, h1);
                MMA_BF16(s1, qhf[kc], h2, h3);
                MMA_BF16(s1, qhf[kc], e2, e3);
                MMA_BF16(s1, qlf[kc], h2, h3);
            }
        }

        const bool needmask = (j * 64 + 63 > qs + wrow);
        float mt0 = -1e30f, mt1 = -1e30f;
#pragma unroll
        for (int nt = 0; nt < 8; nt++) {
            float* s = sacc[nt];
            s[0] *= 0.125f; s[1] *= 0.125f; s[2] *= 0.125f; s[3] *= 0.125f;
            if (needmask) {
                int c0 = j * 64 + nt * 8 + lk;
                if (c0     > r0g) s[0] = -1e30f;
                if (c0 + 1 > r0g) s[1] = -1e30f;
                if (c0     > r1g) s[2] = -1e30f;
                if (c0 + 1 > r1g) s[3] = -1e30f;
            }
            mt0 = fmaxf(mt0, fmaxf(s[0], s[1]));
            mt1 = fmaxf(mt1, fmaxf(s[2], s[3]));
        }
        mt0 = fmaxf(mt0, __shfl_xor_sync(0xFFFFFFFFu, mt0, 1));
        mt0 = fmaxf(mt0, __shfl_xor_sync(0xFFFFFFFFu, mt0, 2));
        mt1 = fmaxf(mt1, __shfl_xor_sync(0xFFFFFFFFu, mt1, 1));
        mt1 = fmaxf(mt1, __shfl_xor_sync(0xFFFFFFFFu, mt1, 2));
        float mn0 = fmaxf(m0, mt0), mn1 = fmaxf(m1, mt1);
        float a0 = __expf(m0 - mn0), a1 = __expf(m1 - mn1);
        m0 = mn0; m1 = mn1;

        float ps0 = 0.0f, ps1 = 0.0f;
        unsigned pah[4][4], pal[4][4];
#pragma unroll
        for (int nt = 0; nt < 8; nt++) {
            float* s = sacc[nt];
            float p0 = __expf(s[0] - mn0), p1 = __expf(s[1] - mn0);
            float p2 = __expf(s[2] - mn1), p3 = __expf(s[3] - mn1);
            ps0 += p0 + p1; ps1 += p2 + p3;
            unsigned h01 = pack_bf16x2(p0, p1);
            unsigned h23 = pack_bf16x2(p2, p3);
            __nv_bfloat162 hb01 = *(__nv_bfloat162*)&h01;
            __nv_bfloat162 hb23 = *(__nv_bfloat162*)&h23;
            unsigned lo01 = pack_bf16x2(p0 - __bfloat162float(hb01.x),
                                        p1 - __bfloat162float(hb01.y));
            unsigned lo23 = pack_bf16x2(p2 - __bfloat162float(hb23.x),
                                        p3 - __bfloat162float(hb23.y));
            int kc = nt >> 1, rlo = (nt & 1) * 2;
            pah[kc][rlo]     = h01;
            pah[kc][rlo + 1] = h23;
            pal[kc][rlo]     = lo01;
            pal[kc][rlo + 1] = lo23;
        }
        ps0 += __shfl_xor_sync(0xFFFFFFFFu, ps0, 1);
        ps0 += __shfl_xor_sync(0xFFFFFFFFu, ps0, 2);
        ps1 += __shfl_xor_sync(0xFFFFFFFFu, ps1, 1);
        ps1 += __shfl_xor_sync(0xFFFFFFFFu, ps1, 2);
        l0 = a0 * l0 + ps0;
        l1 = a1 * l1 + ps1;

#pragma unroll
        for (int nt = 0; nt < 8; nt++) {
            oacc[nt][0] *= a0; oacc[nt][1] *= a0;
            oacc[nt][2] *= a1; oacc[nt][3] *= a1;
        }

        const unsigned vhq = Vh_u + st * 9216u + laneV;
        const unsigned vlq = Vl_u + st * 9216u + laneV;
#pragma unroll
        for (int kc = 0; kc < 4; kc++) {
#pragma unroll
            for (int nt2 = 0; nt2 < 4; nt2++) {
                unsigned h0, h1, h2, h3, e0, e1, e2, e3;
                ldsm4t(h0, h1, h2, h3, vhq + kc * 2304u + nt2 * 32u);
                ldsm4t(e0, e1, e2, e3, vlq + kc * 2304u + nt2 * 32u);
                float* o0 = oacc[2 * nt2];
                float* o1 = oacc[2 * nt2 + 1];
                MMA_BF16(o0, pah[kc], h0, h1);
                MMA_BF16(o0, pah[kc], e0, e1);
                MMA_BF16(o0, pal[kc], h0, h1);
                MMA_BF16(o1, pah[kc], h2, h3);
                MMA_BF16(o1, pah[kc], e2, e3);
                MMA_BF16(o1, pal[kc], h2, h3);
            }
        }
    }

    float i0 = 1.0f / l0, i1 = 1.0f / l1;
    size_t wb0 = (size_t)(b * TT + r0g) * 1024 + h * 64 + lk;
    size_t wb1 = wb0 + (size_t)8 * 1024;
#pragma unroll
    for (int nt = 0; nt < 8; nt++) {
        float v00 = oacc[nt][0] * i0, v01 = oacc[nt][1] * i0;
        float v10 = oacc[nt][2] * i1, v11 = oacc[nt][3] * i1;
        unsigned h0 = pack_bf16x2(v00, v01);
        __nv_bfloat162 hb0 = *(__nv_bfloat162*)&h0;
        unsigned lo0 = pack_bf16x2(v00 - __bfloat162float(hb0.x),
                                   v01 - __bfloat162float(hb0.y));
        unsigned h1 = pack_bf16x2(v10, v11);
        __nv_bfloat162 hb1 = *(__nv_bfloat162*)&h1;
        unsigned lo1 = pack_bf16x2(v10 - __bfloat162float(hb1.x),
                                   v11 - __bfloat162float(hb1.y));
        *(unsigned*)(g_yh + wb0 + nt * 8) = h0;
        *(unsigned*)(g_yl + wb0 + nt * 8) = lo0;
        *(unsigned*)(g_yh + wb1 + nt * 8) = h1;
        *(unsigned*)(g_yl + wb1 + nt * 8) = lo1;
    }
}

extern "C" void kernel_launch(void* const* d_in, const int* in_sizes, int n_in,
                              void* d_out, int out_size)
{
    const float* x  = (const float*)d_in[0];
    const float* Wa = (const float*)d_in[2];
    const float* ba = (const float*)d_in[3];
    const float* Wp = (const float*)d_in[4];
    const float* bp = (const float*)d_in[5];
    float* out = (float*)d_out;

    void *xh, *xl, *Wah, *Wal, *Wph, *Wpl, *qh, *ql, *yh, *yl;
    cudaGetSymbolAddress(&xh, g_xh);   cudaGetSymbolAddress(&xl, g_xl);
    cudaGetSymbolAddress(&Wah, g_Wah); cudaGetSymbolAddress(&Wal, g_Wal);
    cudaGetSymbolAddress(&Wph, g_Wph); cudaGetSymbolAddress(&Wpl, g_Wpl);
    cudaGetSymbolAddress(&qh, g_qh);   cudaGetSymbolAddress(&ql, g_ql);
    cudaGetSymbolAddress(&yh, g_yh);   cudaGetSymbolAddress(&yl, g_yl);

    cudaFuncSetAttribute((const void*)gemm_kernel,
                         cudaFuncAttributeMaxDynamicSharedMemorySize, 75776);
    cudaFuncSetAttribute((const void*)attn_kernel,
                         cudaFuncAttributeMaxDynamicSharedMemorySize, 73728);

    split_kernel<<<8192, 256>>>((const float4*)x,  (__nv_bfloat16*)xh,  (__nv_bfloat16*)xl,  8192 * 1024 / 4);
    split_kernel<<<3072, 256>>>((const float4*)Wa, (__nv_bfloat16*)Wah, (__nv_bfloat16*)Wal, 1024 * 3072 / 4);
    split_kernel<<<1024, 256>>>((const float4*)Wp, (__nv_bfloat16*)Wph, (__nv_bfloat16*)Wpl, 1024 * 1024 / 4);

    gemm_kernel<<<dim3(3072 / 128, 8192 / 128), 256, 75776>>>(
        (const __nv_bfloat16*)xh, (const __nv_bfloat16*)xl,
        (const __nv_bfloat16*)Wah, (const __nv_bfloat16*)Wal,
        ba, nullptr, (__nv_bfloat16*)qh, (__nv_bfloat16*)ql,
        8192, 3072, 1024);

    attn_kernel<<<dim3(TT / 128, 64), 256, 73728>>>();

    gemm_kernel<<<dim3(1024 / 128, 8192 / 128), 256, 75776>>>(
        (const __nv_bfloat16*)yh, (const __nv_bfloat16*)yl,
        (const __nv_bfloat16*)Wph, (const __nv_bfloat16*)Wpl,
        bp, out, nullptr, nullptr,
        8192, 1024, 1024);
}